// round 3
// baseline (speedup 1.0000x reference)
#include <cuda_runtime.h>

// Inverse 2D Haar wavelet (fused conv_transpose chain).
// x:   [8, 256, 128, 128] fp32, subbands LL | HL | LH | HH each 64 channels
// out: [8,  64, 256, 256] fp32
//
// out[2h,2w]     = 0.5*(LL+LH+HL+HH)
// out[2h,2w+1]   = 0.5*(LL-LH+HL-HH)
// out[2h+1,2w]   = 0.5*(LL+LH-HL-HH)
// out[2h+1,2w+1] = 0.5*(LL-LH-HL+HH)
//
// Each thread: float2 of input per subband for TWO adjacent input rows
// (8 independent LDG.64 front-batched -> MLP=8), emits 4 STG.128 into four
// consecutive output rows. All accesses fully contiguous across the warp.
// Streaming cache hints (read-once / write-once data).

#define B_  8
#define C_  64
#define H_  128
#define W_  128
#define HP_ (H_ / 2)               // 64 row-pairs
#define W2_ (W_ / 2)               // 64 float2 per row
#define IN_PLANE   (H_ * W_)       // 16384
#define IN_BSTRIDE (4 * C_ * IN_PLANE)
#define OUT_W      (2 * W_)        // 256
#define OUT_PLANE  (4 * IN_PLANE)  // 65536
#define OUT_BSTRIDE (C_ * OUT_PLANE)

__device__ __forceinline__ float2 ldcs2(const float* p) {
    return __ldcs((const float2*)p);
}

__global__ __launch_bounds__(256) void iwt_kernel(const float* __restrict__ x,
                                                  float* __restrict__ out) {
    int idx = blockIdx.x * blockDim.x + threadIdx.x;
    // idx -> (b, c, hp, w2)
    int w2 = idx & (W2_ - 1);
    int t  = idx >> 6;
    int hp = t & (HP_ - 1);
    t >>= 6;
    int c  = t & (C_ - 1);
    int b  = t >> 6;

    const float* base = x + (long long)b * IN_BSTRIDE + (long long)c * IN_PLANE
                          + (2 * hp) * W_ + (w2 << 1);

    // Front-batched: 8 independent loads (2 rows x 4 subbands)
    float2 ll0 = ldcs2(base);
    float2 hl0 = ldcs2(base + 64  * IN_PLANE);
    float2 lh0 = ldcs2(base + 128 * IN_PLANE);
    float2 hh0 = ldcs2(base + 192 * IN_PLANE);
    float2 ll1 = ldcs2(base + W_);
    float2 hl1 = ldcs2(base + 64  * IN_PLANE + W_);
    float2 lh1 = ldcs2(base + 128 * IN_PLANE + W_);
    float2 hh1 = ldcs2(base + 192 * IN_PLANE + W_);

    float* obase = out + (long long)b * OUT_BSTRIDE + (long long)c * OUT_PLANE
                       + (4 * hp) * OUT_W + (w2 << 2);

    float4 r0, r1, r2, r3;

    // input row 2hp -> output rows 4hp, 4hp+1
    {
        float a = ll0.x, bq = lh0.x, cq = hl0.x, d = hh0.x;
        float apb = a + bq, amb = a - bq, cpd = cq + d, cmd = cq - d;
        r0.x = 0.5f * (apb + cpd);  r0.y = 0.5f * (amb + cmd);
        r1.x = 0.5f * (apb - cpd);  r1.y = 0.5f * (amb - cmd);
    }
    {
        float a = ll0.y, bq = lh0.y, cq = hl0.y, d = hh0.y;
        float apb = a + bq, amb = a - bq, cpd = cq + d, cmd = cq - d;
        r0.z = 0.5f * (apb + cpd);  r0.w = 0.5f * (amb + cmd);
        r1.z = 0.5f * (apb - cpd);  r1.w = 0.5f * (amb - cmd);
    }
    // input row 2hp+1 -> output rows 4hp+2, 4hp+3
    {
        float a = ll1.x, bq = lh1.x, cq = hl1.x, d = hh1.x;
        float apb = a + bq, amb = a - bq, cpd = cq + d, cmd = cq - d;
        r2.x = 0.5f * (apb + cpd);  r2.y = 0.5f * (amb + cmd);
        r3.x = 0.5f * (apb - cpd);  r3.y = 0.5f * (amb - cmd);
    }
    {
        float a = ll1.y, bq = lh1.y, cq = hl1.y, d = hh1.y;
        float apb = a + bq, amb = a - bq, cpd = cq + d, cmd = cq - d;
        r2.z = 0.5f * (apb + cpd);  r2.w = 0.5f * (amb + cmd);
        r3.z = 0.5f * (apb - cpd);  r3.w = 0.5f * (amb - cmd);
    }

    __stcs((float4*)(obase),             r0);
    __stcs((float4*)(obase + OUT_W),     r1);
    __stcs((float4*)(obase + 2 * OUT_W), r2);
    __stcs((float4*)(obase + 3 * OUT_W), r3);
}

extern "C" void kernel_launch(void* const* d_in, const int* in_sizes, int n_in,
                              void* d_out, int out_size) {
    const float* x = (const float*)d_in[0];
    float* out = (float*)d_out;
    const int total = B_ * C_ * HP_ * W2_;   // 2,097,152 threads
    iwt_kernel<<<total / 256, 256>>>(x, out);
}